// round 3
// baseline (speedup 1.0000x reference)
#include <cuda_runtime.h>
#include <cstdint>

#define Tn 4000
#define Bn 16
#define Cn 256
#define G4 1024        // 4*C
#define Mn (Tn*Bn)     // 64000
#define NLAYER 12

// ---------------- scratch (device globals: allocation-free) ----------------
__device__ float g_Xa[(size_t)Mn * Cn];
__device__ float g_Xb[(size_t)Mn * Cn];
__device__ float g_GX[(size_t)Mn * G4];

// ---------------- packed f32x2 helpers ----------------
__device__ __forceinline__ void ffma2(unsigned long long& d, unsigned long long a, unsigned long long b) {
    asm("fma.rn.f32x2 %0, %1, %2, %0;" : "+l"(d) : "l"(a), "l"(b));
}
__device__ __forceinline__ unsigned long long pk(float a, float b) {
    unsigned long long r; asm("mov.b64 %0, {%1,%2};" : "=l"(r) : "f"(a), "f"(b)); return r;
}
__device__ __forceinline__ float2 unpk(unsigned long long v) {
    float2 r; asm("mov.b64 {%0,%1}, %2;" : "=f"(r.x), "=f"(r.y) : "l"(v)); return r;
}

__device__ __forceinline__ float sig_f(float x) {
    return __fdividef(1.f, 1.f + __expf(-x));
}
__device__ __forceinline__ float tanh_f(float x) {
    float z = __expf(-2.f * fabsf(x));
    float t = __fdividef(1.f - z, 1.f + z);
    return (x < 0.f) ? -t : t;
}

__device__ __forceinline__ void st_peer(unsigned laddr, unsigned peer, float v) {
    asm volatile(
        "{\n\t.reg .u32 ra;\n\t"
        "mapa.shared::cluster.u32 ra, %0, %1;\n\t"
        "st.shared::cluster.f32 [ra], %2;\n\t}"
        :: "r"(laddr), "r"(peer), "f"(v) : "memory");
}

// ---------------- transpose in: x(B,C,L) -> X[t][b][c] ----------------
__global__ void tin_kernel(const float* __restrict__ x, float* __restrict__ X) {
    __shared__ float tile[32][33];
    int t0 = blockIdx.x * 32, c0 = blockIdx.y * 32, b = blockIdx.z;
    int tx = threadIdx.x, ty = threadIdx.y;
    #pragma unroll
    for (int i = 0; i < 32; i += 8)
        tile[ty + i][tx] = x[(size_t)b * Cn * Tn + (size_t)(c0 + ty + i) * Tn + t0 + tx];
    __syncthreads();
    #pragma unroll
    for (int i = 0; i < 32; i += 8)
        X[(size_t)(t0 + ty + i) * Bn * Cn + b * Cn + c0 + tx] = tile[tx][ty + i];
}

// ---------------- transpose out: X[t][b][c] -> out(B,C,L) ----------------
__global__ void tout_kernel(const float* __restrict__ X, float* __restrict__ out) {
    __shared__ float tile[32][33];
    int t0 = blockIdx.x * 32, c0 = blockIdx.y * 32, b = blockIdx.z;
    int tx = threadIdx.x, ty = threadIdx.y;
    #pragma unroll
    for (int i = 0; i < 32; i += 8)
        tile[ty + i][tx] = X[(size_t)(t0 + ty + i) * Bn * Cn + b * Cn + c0 + tx];
    __syncthreads();
    #pragma unroll
    for (int i = 0; i < 32; i += 8)
        out[(size_t)b * Cn * Tn + (size_t)(c0 + ty + i) * Tn + t0 + tx] = tile[tx][ty + i];
}

// ---------------- gx GEMM: GX[m][n] = X[m][k]*W[n][k] + bih[n] + bhh[n] ----------------
// M=64000, N=1024, K=256. BM=BN=128, BK=8, 256 threads, 8x8 microtile, FFMA2.
__global__ __launch_bounds__(256, 1) void gemm_gx(
    const float* __restrict__ X, const float* __restrict__ W,
    const float* __restrict__ bih, const float* __restrict__ bhh,
    float* __restrict__ GXo)
{
    __shared__ __align__(16) float As[2][8][128];
    __shared__ __align__(16) float Bs[2][8][128];
    const int m0 = blockIdx.y * 128;
    const int n0 = blockIdx.x * 128;
    const int tid = threadIdx.x;
    const int tx = tid & 15, ty = tid >> 4;
    const int lr = tid >> 1;           // 0..127
    const int lk = (tid & 1) * 4;      // 0 or 4

    const float* Ag = X + (size_t)(m0 + lr) * 256 + lk;
    const float* Bg = W + (size_t)(n0 + lr) * 256 + lk;

    auto load_stage = [&](int s, int kc) {
        float4 av = *reinterpret_cast<const float4*>(Ag + kc * 8);
        float4 bv = *reinterpret_cast<const float4*>(Bg + kc * 8);
        As[s][lk + 0][lr] = av.x; As[s][lk + 1][lr] = av.y;
        As[s][lk + 2][lr] = av.z; As[s][lk + 3][lr] = av.w;
        Bs[s][lk + 0][lr] = bv.x; Bs[s][lk + 1][lr] = bv.y;
        Bs[s][lk + 2][lr] = bv.z; Bs[s][lk + 3][lr] = bv.w;
    };

    unsigned long long acc[8][4];
    #pragma unroll
    for (int i = 0; i < 8; i++)
        #pragma unroll
        for (int j = 0; j < 4; j++) acc[i][j] = 0ull;

    load_stage(0, 0);
    __syncthreads();

    for (int kc = 0; kc < 32; ++kc) {
        int s = kc & 1;
        if (kc < 31) load_stage(s ^ 1, kc + 1);
        #pragma unroll
        for (int k = 0; k < 8; k++) {
            float4 a0 = *reinterpret_cast<const float4*>(&As[s][k][ty * 8]);
            float4 a1 = *reinterpret_cast<const float4*>(&As[s][k][ty * 8 + 4]);
            float4 b0 = *reinterpret_cast<const float4*>(&Bs[s][k][tx * 8]);
            float4 b1 = *reinterpret_cast<const float4*>(&Bs[s][k][tx * 8 + 4]);
            unsigned long long bb0 = pk(b0.x, b0.y), bb1 = pk(b0.z, b0.w);
            unsigned long long bb2 = pk(b1.x, b1.y), bb3 = pk(b1.z, b1.w);
            float av[8] = {a0.x, a0.y, a0.z, a0.w, a1.x, a1.y, a1.z, a1.w};
            #pragma unroll
            for (int i = 0; i < 8; i++) {
                unsigned long long aa = pk(av[i], av[i]);
                ffma2(acc[i][0], aa, bb0);
                ffma2(acc[i][1], aa, bb1);
                ffma2(acc[i][2], aa, bb2);
                ffma2(acc[i][3], aa, bb3);
            }
        }
        __syncthreads();
    }

    float bias[8];
    #pragma unroll
    for (int j = 0; j < 8; j++) {
        int n = n0 + tx * 8 + j;
        bias[j] = __ldg(&bih[n]) + __ldg(&bhh[n]);
    }
    #pragma unroll
    for (int i = 0; i < 8; i++) {
        size_t m = (size_t)(m0 + ty * 8 + i);
        float o[8];
        #pragma unroll
        for (int jp = 0; jp < 4; jp++) {
            float2 v = unpk(acc[i][jp]);
            o[2 * jp] = v.x + bias[2 * jp];
            o[2 * jp + 1] = v.y + bias[2 * jp + 1];
        }
        float4* dst = reinterpret_cast<float4*>(&GXo[m * 1024 + n0 + tx * 8]);
        dst[0] = make_float4(o[0], o[1], o[2], o[3]);
        dst[1] = make_float4(o[4], o[5], o[6], o[7]);
    }
}

// ---------------- persistent LSTM scan ----------------
// grid = 128 CTAs as 16 clusters of 8 (cluster = one batch element).
// CTA rank r owns hidden units [r*32, r*32+32), all 4 gates => 128 W_hh rows in regs.
// 256 threads: row = tid&127 (gate*32+u), khalf = tid>>7 (K split in two halves).
__global__ void __cluster_dims__(8, 1, 1) __launch_bounds__(256, 1)
scan_kernel(const float* __restrict__ Xin, const float* __restrict__ GX,
            const float* __restrict__ Whh, float* __restrict__ Xout, int is_even)
{
    unsigned rank;
    asm("mov.u32 %0, %%cluster_ctarank;" : "=r"(rank));
    const int b = blockIdx.x >> 3;
    const int tid = threadIdx.x;
    const int row = tid & 127;
    const int khalf = tid >> 7;
    const int gidx = row >> 5;
    const int u = row & 31;
    const int grow = gidx * 256 + (int)rank * 32 + u;

    __shared__ __align__(16) float h_s[2][256];
    __shared__ float part_s[128];
    __shared__ float act_s[128];

    // weights resident in registers: 128 fp32 = 32 ulonglong2 per thread
    ulonglong2 w[32];
    const ulonglong2* wp = reinterpret_cast<const ulonglong2*>(Whh + (size_t)grow * 256 + khalf * 128);
    #pragma unroll
    for (int i = 0; i < 32; i++) w[i] = wp[i];

    h_s[0][tid] = 0.f;
    float c_state = 0.f;
    __syncthreads();

    const float* gxp = GX + (size_t)b * 1024 + grow;

    int par = 0;
    for (int t = 0; t < Tn; ++t) {
        // prefetch gx and residual source (consumed after the ~300-cycle dot)
        float gxv = 0.f, xres = 0.f;
        if (khalf == 0) gxv = __ldg(gxp + (size_t)t * (Bn * G4));
        int src, dst;
        if (is_even) { dst = (t % 400) * 10 + (t / 400); src = dst; }
        else         { src = t; dst = Tn - 1 - t; }
        if (tid < 32)
            xres = __ldg(Xin + ((size_t)src * Bn + b) * Cn + (int)rank * 32 + tid);

        // split-K dot: 128 MACs per thread via FFMA2
        const ulonglong2* h2 = reinterpret_cast<const ulonglong2*>(&h_s[par][khalf << 7]);
        unsigned long long a0 = 0ull, a1 = 0ull, a2 = 0ull, a3 = 0ull;
        #pragma unroll
        for (int i = 0; i < 32; i += 2) {
            ulonglong2 hv0 = h2[i];
            ulonglong2 hv1 = h2[i + 1];
            ffma2(a0, w[i].x, hv0.x);
            ffma2(a1, w[i].y, hv0.y);
            ffma2(a2, w[i + 1].x, hv1.x);
            ffma2(a3, w[i + 1].y, hv1.y);
        }
        float2 f0 = unpk(a0), f1 = unpk(a1), f2 = unpk(a2), f3 = unpk(a3);
        float partial = ((f0.x + f0.y) + (f1.x + f1.y)) + ((f2.x + f2.y) + (f3.x + f3.y));

        if (khalf) part_s[row] = partial;
        __syncthreads();

        if (khalf == 0) {
            float tot = partial + part_s[row] + gxv;
            act_s[row] = (gidx == 2) ? tanh_f(tot) : sig_f(tot);
        }
        __syncthreads();

        if (tid < 32) {
            float iv = act_s[tid], fv = act_s[32 + tid], gv = act_s[64 + tid], ov = act_s[96 + tid];
            c_state = fv * c_state + iv * gv;
            float hv = ov * tanh_f(c_state);
            int nb = par ^ 1;
            int col = (int)rank * 32 + tid;
            h_s[nb][col] = hv;
            unsigned laddr = (unsigned)__cvta_generic_to_shared(&h_s[nb][col]);
            #pragma unroll
            for (unsigned p = 0; p < 8; p++)
                if (p != rank) st_peer(laddr, p, hv);
            Xout[((size_t)dst * Bn + b) * Cn + col] = xres + hv;
        }

        // cluster-wide barrier: publishes DSMEM h writes, separates double buffers
        asm volatile("barrier.cluster.arrive.aligned;" ::: "memory");
        asm volatile("barrier.cluster.wait.aligned;" ::: "memory");
        par ^= 1;
    }
}

// ---------------- launch ----------------
extern "C" void kernel_launch(void* const* d_in, const int* in_sizes, int n_in,
                              void* d_out, int out_size) {
    const float* x    = (const float*)d_in[0];
    const float* w_ih = (const float*)d_in[1];
    const float* w_hh = (const float*)d_in[2];
    const float* b_ih = (const float*)d_in[3];
    const float* b_hh = (const float*)d_in[4];

    float *Xa, *Xb, *GXp;
    cudaGetSymbolAddress((void**)&Xa, g_Xa);
    cudaGetSymbolAddress((void**)&Xb, g_Xb);
    cudaGetSymbolAddress((void**)&GXp, g_GX);
    float* Xbuf[2] = {Xa, Xb};

    dim3 tgrid(Tn / 32, Cn / 32, Bn), tblk(32, 8);
    tin_kernel<<<tgrid, tblk>>>(x, Xbuf[0]);

    int cur = 0;
    for (int l = 0; l < NLAYER; ++l) {
        gemm_gx<<<dim3(G4 / 128, Mn / 128), 256>>>(
            Xbuf[cur], w_ih + (size_t)l * G4 * Cn,
            b_ih + (size_t)l * G4, b_hh + (size_t)l * G4, GXp);
        scan_kernel<<<128, 256>>>(
            Xbuf[cur], GXp, w_hh + (size_t)l * G4 * Cn,
            Xbuf[cur ^ 1], (l & 1) == 0 ? 1 : 0);
        cur ^= 1;
    }

    tout_kernel<<<tgrid, tblk>>>(Xbuf[cur], (float*)d_out);
}